// round 3
// baseline (speedup 1.0000x reference)
#include <cuda_runtime.h>
#include <cuda_bf16.h>
#include <cuda_fp16.h>

#define SRC_LEN 256
#define TRG_LEN 256
#define BATCH   32
#define HID     512
#define ATT     128

// Scratch for projected activations (device globals; no allocation allowed).
// Layout: [(len_idx * BATCH + b) * ATT + a]
__device__ float g_enc_att[SRC_LEN * BATCH * ATT];
__device__ float g_dec_att[TRG_LEN * BATCH * ATT];

typedef unsigned long long u64;

// ---- packed f32x2 helpers (Blackwell FFMA2 path; ptxas never emits these from C++) ----
__device__ __forceinline__ u64 pack2(float lo, float hi) {
    u64 r; asm("mov.b64 %0, {%1, %2};" : "=l"(r) : "f"(lo), "f"(hi)); return r;
}
__device__ __forceinline__ u64 dup2(float x) {
    u64 r; asm("mov.b64 %0, {%1, %1};" : "=l"(r) : "f"(x)); return r;
}
__device__ __forceinline__ void ffma2(u64& d, u64 a, u64 b) {
    asm("fma.rn.f32x2 %0, %1, %2, %0;" : "+l"(d) : "l"(a), "l"(b));
}
__device__ __forceinline__ float2 unpk2(u64 v) {
    float2 r; asm("mov.b64 {%0, %1}, %2;" : "=f"(r.x), "=f"(r.y) : "l"(v)); return r;
}

// ---- fp16x2 helpers for the score pass ----
__device__ __forceinline__ unsigned int pack_h2(float lo, float hi) {
    // cvt.rn.f16x2.f32 d, a, b  ->  d.h1 = cvt(a), d.h0 = cvt(b)
    unsigned int r; asm("cvt.rn.f16x2.f32 %0, %1, %2;" : "=r"(r) : "f"(hi), "f"(lo)); return r;
}
__device__ __forceinline__ unsigned int tanh_h2(unsigned int x) {
    unsigned int y; asm("tanh.approx.f16x2 %0, %1;" : "=r"(y) : "r"(x)); return y;
}
__device__ __forceinline__ unsigned int hfma2_(unsigned int a, unsigned int b, unsigned int c) {
    unsigned int d; asm("fma.rn.f16x2 %0, %1, %2, %3;" : "=r"(d) : "r"(a), "r"(b), "r"(c)); return d;
}
__device__ __forceinline__ float2 h2_to_f2(unsigned int h) {
    float2 r;
    asm("{ .reg .f16 lo, hi;\n\t"
        "  mov.b32 {lo, hi}, %2;\n\t"
        "  cvt.f32.f16 %0, lo;\n\t"
        "  cvt.f32.f16 %1, hi; }"
        : "=f"(r.x), "=f"(r.y) : "r"(h));
    return r;
}

// ---------------------------------------------------------------------------
// Projection GEMM: C[row][n] = sum_h X[row][h] * W[n][h]  (+ bias if z==1)
// X: 8192 x 512 row-major, W: 128 x 512 row-major, C: 8192 x 128.
// BM=64, BN=64, BK=32, 256 threads, 4x4 register tile per thread, inner loop
// uses packed fma.rn.f32x2 (acc packed along m; a-pairs fall out of LDS.128).
// grid = (128, 2, 2 [enc|dec])
// ---------------------------------------------------------------------------
__global__ __launch_bounds__(256) void proj_kernel(
    const float* __restrict__ dec_out,
    const float* __restrict__ enc_outs,
    const float* __restrict__ W_s,
    const float* __restrict__ W_t,
    const float* __restrict__ b_t)
{
    const int z = blockIdx.z;
    const float* __restrict__ X = z ? dec_out : enc_outs;
    const float* __restrict__ W = z ? W_t : W_s;
    float* __restrict__ C = z ? g_dec_att : g_enc_att;

    __shared__ float As[32][64];  // [k][m]
    __shared__ float Bs[32][64];  // [k][n]

    const int tid = threadIdx.x;
    const int tx = tid & 15;       // n-dim thread
    const int ty = tid >> 4;       // m-dim thread
    const int m0 = blockIdx.x * 64;
    const int n0 = blockIdx.y * 64;

    u64 acc2[2][4];                // [m-pair][n]
    const u64 z64 = dup2(0.0f);
    #pragma unroll
    for (int p = 0; p < 2; p++)
        #pragma unroll
        for (int j = 0; j < 4; j++) acc2[p][j] = z64;

    for (int k0 = 0; k0 < HID; k0 += 32) {
        // Load A tile (64x32) and B tile (64x32): 512 float4 each, 2 per thread.
        #pragma unroll
        for (int r = 0; r < 2; r++) {
            const int i  = (tid << 1) + r;     // 0..511
            const int m  = i >> 3;             // row within tile
            const int kq = i & 7;              // float4 index within 32-k chunk
            const float4 va = *reinterpret_cast<const float4*>(
                X + (size_t)(m0 + m) * HID + k0 + (kq << 2));
            As[kq * 4 + 0][m] = va.x;
            As[kq * 4 + 1][m] = va.y;
            As[kq * 4 + 2][m] = va.z;
            As[kq * 4 + 3][m] = va.w;
            const float4 vb = *reinterpret_cast<const float4*>(
                W + (size_t)(n0 + m) * HID + k0 + (kq << 2));
            Bs[kq * 4 + 0][m] = vb.x;
            Bs[kq * 4 + 1][m] = vb.y;
            Bs[kq * 4 + 2][m] = vb.z;
            Bs[kq * 4 + 3][m] = vb.w;
        }
        __syncthreads();

        #pragma unroll
        for (int kk = 0; kk < 32; kk++) {
            const float4 av = *reinterpret_cast<const float4*>(&As[kk][ty << 2]);
            const float4 bv = *reinterpret_cast<const float4*>(&Bs[kk][tx << 2]);
            const u64 a01 = pack2(av.x, av.y);
            const u64 a23 = pack2(av.z, av.w);
            const u64 bd0 = dup2(bv.x);
            const u64 bd1 = dup2(bv.y);
            const u64 bd2 = dup2(bv.z);
            const u64 bd3 = dup2(bv.w);
            ffma2(acc2[0][0], a01, bd0); ffma2(acc2[1][0], a23, bd0);
            ffma2(acc2[0][1], a01, bd1); ffma2(acc2[1][1], a23, bd1);
            ffma2(acc2[0][2], a01, bd2); ffma2(acc2[1][2], a23, bd2);
            ffma2(acc2[0][3], a01, bd3); ffma2(acc2[1][3], a23, bd3);
        }
        __syncthreads();
    }

    // Unpack: acc2[p][j] holds rows (ty*4+2p, ty*4+2p+1), col tx*4+j.
    float c[4][4];
    #pragma unroll
    for (int p = 0; p < 2; p++)
        #pragma unroll
        for (int j = 0; j < 4; j++) {
            const float2 t = unpk2(acc2[p][j]);
            c[2 * p][j]     = t.x;
            c[2 * p + 1][j] = t.y;
        }

    float bias[4] = {0.f, 0.f, 0.f, 0.f};
    if (z) {
        #pragma unroll
        for (int j = 0; j < 4; j++) bias[j] = b_t[n0 + (tx << 2) + j];
    }
    #pragma unroll
    for (int i = 0; i < 4; i++) {
        float4 o;
        o.x = c[i][0] + bias[0];
        o.y = c[i][1] + bias[1];
        o.z = c[i][2] + bias[2];
        o.w = c[i][3] + bias[3];
        *reinterpret_cast<float4*>(
            C + (size_t)(m0 + (ty << 2) + i) * ATT + n0 + (tx << 2)) = o;
    }
}

// ---------------------------------------------------------------------------
// Score kernel: out[t][b][s] = sum_a v[a] * tanh(dec_att[t,b,a] + enc_att[s,b,a])
// Tile: 32 t x 32 s per block, one b per block.z. 256 threads, 2x2 per thread.
// tanh in packed fp16x2 (halves MUFU ops); adds in f32; fp16 accumulation
// flushed to f32 every 4 a-steps to bound rounding error.
// grid = (SRC/32 = 8, TRG/32 = 8, BATCH = 32)
// ---------------------------------------------------------------------------
__global__ __launch_bounds__(256) void score_kernel(
    const float* __restrict__ v_a,
    float* __restrict__ out)
{
    __shared__ float sh_e[ATT][34];         // pad 34 keeps 8B alignment for float2 loads
    __shared__ float sh_d[ATT][34];
    __shared__ unsigned int sh_v2[ATT];     // (v, v) packed fp16x2

    const int tid = threadIdx.x;
    const int b = blockIdx.z;
    const int s_base = blockIdx.x * 32;
    const int t_base = blockIdx.y * 32;

    // Cooperative tile load: 32 rows x 128 a, vectorized float4 (1024 per array).
    for (int idx = tid; idx < 32 * 32; idx += 256) {
        const int i  = idx >> 5;      // row within tile
        const int a4 = idx & 31;      // float4 index along a
        const float4 ev = *reinterpret_cast<const float4*>(
            g_enc_att + ((size_t)(s_base + i) * BATCH + b) * ATT + (a4 << 2));
        sh_e[a4 * 4 + 0][i] = ev.x;
        sh_e[a4 * 4 + 1][i] = ev.y;
        sh_e[a4 * 4 + 2][i] = ev.z;
        sh_e[a4 * 4 + 3][i] = ev.w;
        const float4 dv = *reinterpret_cast<const float4*>(
            g_dec_att + ((size_t)(t_base + i) * BATCH + b) * ATT + (a4 << 2));
        sh_d[a4 * 4 + 0][i] = dv.x;
        sh_d[a4 * 4 + 1][i] = dv.y;
        sh_d[a4 * 4 + 2][i] = dv.z;
        sh_d[a4 * 4 + 3][i] = dv.w;
    }
    if (tid < ATT) {
        const float v = v_a[tid];
        sh_v2[tid] = pack_h2(v, v);
    }
    __syncthreads();

    const int tx = tid & 15;         // s-dim
    const int ty = tid >> 4;         // t-dim
    const int sl = tx << 1;
    const int tl = ty << 1;

    float acc00 = 0.f, acc01 = 0.f, acc10 = 0.f, acc11 = 0.f;

    #pragma unroll
    for (int ac = 0; ac < ATT; ac += 4) {
        unsigned int a16_0 = 0u, a16_1 = 0u;   // fp16x2 chunk accumulators
        #pragma unroll
        for (int k = 0; k < 4; k++) {
            const int a = ac + k;
            const float2 e2 = *reinterpret_cast<const float2*>(&sh_e[a][sl]);
            const float d0 = sh_d[a][tl];
            const float d1 = sh_d[a][tl + 1];
            const unsigned int v2 = sh_v2[a];
            const unsigned int x0 = pack_h2(d0 + e2.x, d0 + e2.y);
            const unsigned int x1 = pack_h2(d1 + e2.x, d1 + e2.y);
            const unsigned int t0 = tanh_h2(x0);
            const unsigned int t1 = tanh_h2(x1);
            a16_0 = hfma2_(v2, t0, a16_0);
            a16_1 = hfma2_(v2, t1, a16_1);
        }
        const float2 f0 = h2_to_f2(a16_0);   // (s=sl, s=sl+1) for t=tl
        const float2 f1 = h2_to_f2(a16_1);   // same for t=tl+1
        acc00 += f0.x; acc01 += f0.y;
        acc10 += f1.x; acc11 += f1.y;
    }

    const int tg = t_base + tl;
    const int sg = s_base + sl;
    float* o0 = out + ((size_t)tg * BATCH + b) * SRC_LEN + sg;
    float2 r0; r0.x = acc00; r0.y = acc01;
    *reinterpret_cast<float2*>(o0) = r0;
    float* o1 = o0 + (size_t)BATCH * SRC_LEN;   // t+1
    float2 r1; r1.x = acc10; r1.y = acc11;
    *reinterpret_cast<float2*>(o1) = r1;
}

extern "C" void kernel_launch(void* const* d_in, const int* in_sizes, int n_in,
                              void* d_out, int out_size)
{
    const float* dec_out  = (const float*)d_in[0];  // (256, 32, 512)
    const float* enc_outs = (const float*)d_in[1];  // (256, 32, 512)
    const float* W_s      = (const float*)d_in[2];  // (128, 512)
    const float* W_t      = (const float*)d_in[3];  // (128, 512)
    const float* b_t      = (const float*)d_in[4];  // (128,)
    const float* v_a      = (const float*)d_in[5];  // (128, 1)
    float* out = (float*)d_out;                     // (256, 32, 256)

    (void)in_sizes; (void)n_in; (void)out_size;

    proj_kernel<<<dim3(128, 2, 2), 256>>>(dec_out, enc_outs, W_s, W_t, b_t);
    score_kernel<<<dim3(SRC_LEN / 32, TRG_LEN / 32, BATCH), 256>>>(v_a, out);
}